// round 5
// baseline (speedup 1.0000x reference)
#include <cuda_runtime.h>
#include <math.h>

#define Bn 4
#define CI 128
#define CO 128
#define Hn 128
#define Wn 128
#define HW (Hn*Wn)
#define KK 9
#define PIX 32
#define CIP (CI + 4)     // padded row for conflict-free STS.128

// packed fp32x2 helpers (Blackwell sm_103a)
#define PACKF2(d, a, b) asm("mov.b64 %0, {%1, %2};" : "=l"(d) : "f"(a), "f"(b))
#define FMAF2(d, a, b, c) asm("fma.rn.f32x2 %0, %1, %2, %3;" : "=l"(d) : "l"(a), "l"(b), "l"(c))
union F2U { unsigned long long u; float2 f; };

// ---------------- scratch (static device allocations, allowed) ----------------
__device__ __align__(16) float g_xT[Bn*HW*CI];       // x in NHWC          33.5 MB
__device__ __align__(16) float g_offp[2][Bn*18*HW];  // partial offset conv  9.4 MB
__device__ __align__(16) float g_wT[KK*CI*CO];       // w_dcn [k][c4][o][4] 0.6 MB
__device__ __align__(16) float g_conv[Bn*CO*HW];     // pre-BN output      33.5 MB
__device__ float g_scale[CO];
__device__ float g_shift[CO];

// ---------------- K1: NCHW -> NHWC transpose of x ----------------
__global__ void k_transpose_x(const float* __restrict__ in) {
    __shared__ float t[32][33];
    int wb = blockIdx.x * 32, cb = blockIdx.y * 32;
    int by = blockIdx.z;                 // b*Hn + y
    int b = by >> 7, y = by & 127;
    t[threadIdx.y][threadIdx.x] =
        in[((b*CI + cb + threadIdx.y)*Hn + y)*Wn + wb + threadIdx.x];
    __syncthreads();
    g_xT[(by*Wn + wb + threadIdx.y)*CI + cb + threadIdx.x] = t[threadIdx.x][threadIdx.y];
}

// ---------------- K2: w_dcn [o][c][k] -> [k][c>>2][o][c&3] ----------------
__global__ void k_transpose_w(const float* __restrict__ w) {
    int i = blockIdx.x * blockDim.x + threadIdx.x;
    if (i >= CO*CI*KK) return;
    int o = i / (CI*KK);
    int r = i % (CI*KK);
    int c = r / KK;
    int kk = r % KK;
    g_wT[((kk*(CI/4) + (c >> 2))*CO + o)*4 + (c & 3)] = w[i];
}

// ---------------- K3: offset conv (18 out ch, 3x3, pad 1), CI split over z ----------------
__global__ __launch_bounds__(128) void k_offset_conv(
    const float* __restrict__ x, const float* __restrict__ w_off,
    const float* __restrict__ b_off) {
    __shared__ __align__(16) float sw[64*9*18];      // 41.5 KB chunk of weights
    int h = blockIdx.x, b = blockIdx.y, z = blockIdx.z;
    int c0 = z * 64;
    int w = threadIdx.x;

    unsigned long long acc2[9];
#pragma unroll
    for (int j = 0; j < 9; j++) acc2[j] = 0ull;      // == (0.0f, 0.0f)

    for (int e = threadIdx.x; e < 64*9*18; e += 128) {
        int cl = e / 162, r = e % 162, t = r / 18, j = r % 18;
        sw[e] = w_off[((j*CI + c0 + cl)*3 + t/3)*3 + t%3];
    }
    __syncthreads();
    for (int cl = 0; cl < 64; cl++) {
        const float* xp = x + (size_t)(b*CI + c0 + cl)*HW;
#pragma unroll
        for (int t = 0; t < 9; t++) {
            int yy = h + t/3 - 1;
            int xx = w + t%3 - 1;
            float xv = (yy >= 0 && yy < Hn && xx >= 0 && xx < Wn)
                     ? xp[yy*Wn + xx] : 0.f;
            unsigned long long xv2;
            PACKF2(xv2, xv, xv);
            const unsigned long long* swp =
                (const unsigned long long*)&sw[(cl*9 + t)*18];
#pragma unroll
            for (int j = 0; j < 9; j++) FMAF2(acc2[j], xv2, swp[j], acc2[j]);
        }
    }
#pragma unroll
    for (int jj = 0; jj < 9; jj++) {
        F2U u; u.u = acc2[jj];
        float b0 = (z == 0) ? b_off[2*jj]     : 0.f;
        float b1 = (z == 0) ? b_off[2*jj + 1] : 0.f;
        g_offp[z][((b*18 + 2*jj    )*Hn + h)*Wn + w] = u.f.x + b0;
        g_offp[z][((b*18 + 2*jj + 1)*Hn + h)*Wn + w] = u.f.y + b1;
    }
}

// ---------------- K4: fused deformable sampling + GEMM (f32x2 over channels) ----------------
// grid (Wn/PIX, Hn, Bn); 128 threads.
// thread owns 4 out channels (og+32i) x 8 pixels (pg*8..pg*8+7).
// accumulator = f32x2 (even-c partial, odd-c partial); horizontal add at end.
__global__ __launch_bounds__(128) void k_main() {
    const int w0  = blockIdx.x * PIX;
    const int h   = blockIdx.y;
    const int b   = blockIdx.z;
    const int tid = threadIdx.x;
    const int og  = tid & 31;
    const int pg  = tid >> 5;

    __shared__ __align__(16) float sS[PIX][CIP];     // sampled[pix][c], padded
    __shared__ int   sIdx[4][PIX];
    __shared__ float sWt[4][PIX];

    unsigned long long acc0[8], acc1[8], acc2[8], acc3[8];
#pragma unroll
    for (int p = 0; p < 8; p++) { acc0[p]=0ull; acc1[p]=0ull; acc2[p]=0ull; acc3[p]=0ull; }

    for (int k = 0; k < KK; k++) {
        // --- per-pixel corner index/weight setup (32 threads) ---
        if (tid < PIX) {
            int w = w0 + tid;
            int oidx = ((b*18 + 2*k)*Hn + h)*Wn + w;
            float dy = g_offp[0][oidx]      + g_offp[1][oidx];
            float dx = g_offp[0][oidx + HW] + g_offp[1][oidx + HW];
            float ys = (float)(h - 1 + (k / 3)) + dy;
            float xs = (float)(w - 1 + (k % 3)) + dx;
            float y0f = floorf(ys), x0f = floorf(xs);
            float wy = ys - y0f, wx = xs - x0f;
            int y0 = (int)y0f, x0 = (int)x0f;
            int y1 = y0 + 1, x1 = x0 + 1;
            float vy0 = (y0 >= 0 && y0 < Hn) ? 1.f : 0.f;
            float vy1 = (y1 >= 0 && y1 < Hn) ? 1.f : 0.f;
            float vx0 = (x0 >= 0 && x0 < Wn) ? 1.f : 0.f;
            float vx1 = (x1 >= 0 && x1 < Wn) ? 1.f : 0.f;
            int y0c = min(max(y0, 0), Hn-1), y1c = min(max(y1, 0), Hn-1);
            int x0c = min(max(x0, 0), Wn-1), x1c = min(max(x1, 0), Wn-1);
            int base = b * HW;
            sIdx[0][tid] = (base + y0c*Wn + x0c)*CI;
            sIdx[1][tid] = (base + y0c*Wn + x1c)*CI;
            sIdx[2][tid] = (base + y1c*Wn + x0c)*CI;
            sIdx[3][tid] = (base + y1c*Wn + x1c)*CI;
            sWt[0][tid] = (1.f - wy)*(1.f - wx)*vy0*vx0;
            sWt[1][tid] = (1.f - wy)*wx       *vy0*vx1;
            sWt[2][tid] = wy       *(1.f - wx)*vy1*vx0;
            sWt[3][tid] = wy       *wx        *vy1*vx1;
        }
        __syncthreads();

        // --- sampling: warp = 4 pixels x 8 c-lanes (coalesced 128B per corner) ---
#pragma unroll
        for (int it = 0; it < 8; it++) {
            int cc  = (it >> 1) * 32;
            int pp  = (it & 1) * 16;
            int pix = pp + (tid >> 3);
            int c   = cc + (tid & 7) * 4;
            int i0 = sIdx[0][pix], i1 = sIdx[1][pix];
            int i2 = sIdx[2][pix], i3 = sIdx[3][pix];
            float w00 = sWt[0][pix], w01 = sWt[1][pix];
            float w10 = sWt[2][pix], w11 = sWt[3][pix];
            float4 p0 = *(const float4*)(g_xT + i0 + c);
            float4 p1 = *(const float4*)(g_xT + i1 + c);
            float4 p2 = *(const float4*)(g_xT + i2 + c);
            float4 p3 = *(const float4*)(g_xT + i3 + c);
            float4 v;
            v.x = w00*p0.x + w01*p1.x + w10*p2.x + w11*p3.x;
            v.y = w00*p0.y + w01*p1.y + w10*p2.y + w11*p3.y;
            v.z = w00*p0.z + w01*p1.z + w10*p2.z + w11*p3.z;
            v.w = w00*p0.w + w01*p1.w + w10*p2.w + w11*p3.w;
            *(float4*)(&sS[pix][c]) = v;
        }
        __syncthreads();

        // --- GEMM: 4 out-channels x 8 pixels, f32x2 over channel pairs ---
        // per c4: 4x LDG.128 (weights, reinterpret as 2 f32x2) +
        //         8x LDS.128 (samples, reinterpret as 2 f32x2) + 64 FMA2
        const float* wk = g_wT + k*(CI/4)*CO*4;
        const float* srow = &sS[pg*8][0];
#pragma unroll 2
        for (int c4 = 0; c4 < CI/4; c4++) {
            ulonglong2 q0 = *(const ulonglong2*)(wk + (c4*CO + og      )*4);
            ulonglong2 q1 = *(const ulonglong2*)(wk + (c4*CO + og + 32 )*4);
            ulonglong2 q2 = *(const ulonglong2*)(wk + (c4*CO + og + 64 )*4);
            ulonglong2 q3 = *(const ulonglong2*)(wk + (c4*CO + og + 96 )*4);
#pragma unroll
            for (int p = 0; p < 8; p++) {
                ulonglong2 s = *(const ulonglong2*)(srow + p*CIP + c4*4);
                FMAF2(acc0[p], q0.x, s.x, acc0[p]);
                FMAF2(acc0[p], q0.y, s.y, acc0[p]);
                FMAF2(acc1[p], q1.x, s.x, acc1[p]);
                FMAF2(acc1[p], q1.y, s.y, acc1[p]);
                FMAF2(acc2[p], q2.x, s.x, acc2[p]);
                FMAF2(acc2[p], q2.y, s.y, acc2[p]);
                FMAF2(acc3[p], q3.x, s.x, acc3[p]);
                FMAF2(acc3[p], q3.y, s.y, acc3[p]);
            }
        }
    }

    // horizontal add (even+odd channel partials) and write out
    float v0[8], v1[8], v2[8], v3[8];
#pragma unroll
    for (int p = 0; p < 8; p++) {
        F2U u;
        u.u = acc0[p]; v0[p] = u.f.x + u.f.y;
        u.u = acc1[p]; v1[p] = u.f.x + u.f.y;
        u.u = acc2[p]; v2[p] = u.f.x + u.f.y;
        u.u = acc3[p]; v3[p] = u.f.x + u.f.y;
    }
    size_t pbase = (size_t)(b*CO)*HW + h*Wn + w0 + pg*8;
    float* d0 = g_conv + pbase + (size_t)(og      )*HW;
    float* d1 = g_conv + pbase + (size_t)(og + 32 )*HW;
    float* d2 = g_conv + pbase + (size_t)(og + 64 )*HW;
    float* d3 = g_conv + pbase + (size_t)(og + 96 )*HW;
    *(float4*)(d0)     = make_float4(v0[0], v0[1], v0[2], v0[3]);
    *(float4*)(d0 + 4) = make_float4(v0[4], v0[5], v0[6], v0[7]);
    *(float4*)(d1)     = make_float4(v1[0], v1[1], v1[2], v1[3]);
    *(float4*)(d1 + 4) = make_float4(v1[4], v1[5], v1[6], v1[7]);
    *(float4*)(d2)     = make_float4(v2[0], v2[1], v2[2], v2[3]);
    *(float4*)(d2 + 4) = make_float4(v2[4], v2[5], v2[6], v2[7]);
    *(float4*)(d3)     = make_float4(v3[0], v3[1], v3[2], v3[3]);
    *(float4*)(d3 + 4) = make_float4(v3[4], v3[5], v3[6], v3[7]);
}

// ---------------- K5: BN stats per channel ----------------
__global__ void k_bn_stats(const float* __restrict__ gamma,
                           const float* __restrict__ beta) {
    int o = blockIdx.x, tid = threadIdx.x;   // 256 threads
    float s = 0.f, s2 = 0.f;
    for (int b = 0; b < Bn; b++) {
        const float* p = g_conv + (size_t)(b*CO + o)*HW;
        for (int i = tid; i < HW; i += 256) {
            float v = p[i];
            s += v;
            s2 = fmaf(v, v, s2);
        }
    }
    __shared__ float rs[8], rs2[8];
#pragma unroll
    for (int off = 16; off; off >>= 1) {
        s  += __shfl_down_sync(0xffffffffu, s,  off);
        s2 += __shfl_down_sync(0xffffffffu, s2, off);
    }
    if ((tid & 31) == 0) { rs[tid >> 5] = s; rs2[tid >> 5] = s2; }
    __syncthreads();
    if (tid < 32) {
        s  = (tid < 8) ? rs[tid]  : 0.f;
        s2 = (tid < 8) ? rs2[tid] : 0.f;
#pragma unroll
        for (int off = 4; off; off >>= 1) {
            s  += __shfl_down_sync(0xffffffffu, s,  off);
            s2 += __shfl_down_sync(0xffffffffu, s2, off);
        }
        if (tid == 0) {
            float inv_n = 1.f / (float)(Bn*HW);
            float mean = s * inv_n;
            float var  = s2 * inv_n - mean*mean;
            float r = 1.f / sqrtf(var + 0.001f);
            float sc = gamma[o] * r;
            g_scale[o] = sc;
            g_shift[o] = beta[o] - mean*sc;
        }
    }
}

// ---------------- K6: apply BN + ReLU ----------------
__global__ void k_bn_apply(float* __restrict__ out) {
    int i = blockIdx.x * blockDim.x + threadIdx.x;   // float4 index
    int ch = (i >> 12) & 127;                        // plane = 16384 elems = 4096 float4
    float4 v = ((const float4*)g_conv)[i];
    float sc = g_scale[ch], sh = g_shift[ch];
    v.x = fmaxf(fmaf(v.x, sc, sh), 0.f);
    v.y = fmaxf(fmaf(v.y, sc, sh), 0.f);
    v.z = fmaxf(fmaf(v.z, sc, sh), 0.f);
    v.w = fmaxf(fmaf(v.w, sc, sh), 0.f);
    ((float4*)out)[i] = v;
}

// ---------------- launch ----------------
extern "C" void kernel_launch(void* const* d_in, const int* in_sizes, int n_in,
                              void* d_out, int out_size) {
    const float* x     = (const float*)d_in[0];
    const float* w_off = (const float*)d_in[1];
    const float* b_off = (const float*)d_in[2];
    const float* w_dcn = (const float*)d_in[3];
    const float* gamma = (const float*)d_in[4];
    const float* beta  = (const float*)d_in[5];
    float* out = (float*)d_out;

    k_transpose_x<<<dim3(Wn/32, CI/32, Bn*Hn), dim3(32, 32)>>>(x);
    k_transpose_w<<<(CO*CI*KK + 255)/256, 256>>>(w_dcn);
    k_offset_conv<<<dim3(Hn, Bn, 2), 128>>>(x, w_off, b_off);
    k_main<<<dim3(Wn/PIX, Hn, Bn), 128>>>();
    k_bn_stats<<<CO, 256>>>(gamma, beta);
    k_bn_apply<<<(Bn*CO*HW/4)/256, 256>>>(out);
}